// round 2
// baseline (speedup 1.0000x reference)
#include <cuda_runtime.h>
#include <math.h>

// Problem constants
#define BSZ 32
#define SSZ 512
#define DSZ 1024
#define LSZ 3
#define NTOK (BSZ * SSZ)   // 16384
#define NPAIR (NTOK / 2)   // 8192
#define INV_SQRT2f 0.70710678118654752440f
#define LN_EPSf 1e-5f

// Scratch (device globals: no allocation allowed in kernel_launch)
__device__ float g_H[(size_t)NTOK * DSZ];        // hidden state (64 MB)
__device__ float g_U[(size_t)NTOK * DSZ];        // silu(hidden)  (64 MB)
__device__ float g_P[(size_t)NPAIR * 2 * DSZ];   // [cA|cD] basis (64 MB)
__device__ float g_C1[(size_t)NTOK * DSZ];       // base GEMM out (64 MB)
__device__ float g_C2[(size_t)NPAIR * DSZ];      // wav GEMM out  (32 MB)

__device__ __forceinline__ float silu_f(float x) {
    return x / (1.0f + __expf(-x));
}

// ---------------------------------------------------------------------------
// U = silu(in), elementwise (float4)
// ---------------------------------------------------------------------------
__global__ void __launch_bounds__(256) silu_kernel(const float* __restrict__ in,
                                                   float* __restrict__ out) {
    size_t i = ((size_t)blockIdx.x * blockDim.x + threadIdx.x) * 4;
    float4 v = *reinterpret_cast<const float4*>(in + i);
    v.x = silu_f(v.x); v.y = silu_f(v.y); v.z = silu_f(v.z); v.w = silu_f(v.w);
    *reinterpret_cast<float4*>(out + i) = v;
}

// ---------------------------------------------------------------------------
// P[p] = [cA_p | cD_p], cA=(e+o)/sqrt2, cD=(e-o)/sqrt2, pairs are global
// consecutive even/odd rows (S even => pairing never crosses batches).
// ---------------------------------------------------------------------------
__global__ void __launch_bounds__(256) pairs_kernel(const float* __restrict__ Hin,
                                                    float* __restrict__ P) {
    size_t idx = (size_t)blockIdx.x * blockDim.x + threadIdx.x;  // over NPAIR*DSZ/4
    int k4 = (int)(idx % (DSZ / 4));
    size_t p = idx / (DSZ / 4);
    float4 e = *reinterpret_cast<const float4*>(Hin + (2 * p) * DSZ + k4 * 4);
    float4 o = *reinterpret_cast<const float4*>(Hin + (2 * p + 1) * DSZ + k4 * 4);
    float4 a, d;
    a.x = (e.x + o.x) * INV_SQRT2f; a.y = (e.y + o.y) * INV_SQRT2f;
    a.z = (e.z + o.z) * INV_SQRT2f; a.w = (e.w + o.w) * INV_SQRT2f;
    d.x = (e.x - o.x) * INV_SQRT2f; d.y = (e.y - o.y) * INV_SQRT2f;
    d.z = (e.z - o.z) * INV_SQRT2f; d.w = (e.w - o.w) * INV_SQRT2f;
    float* Pr = P + p * (2 * DSZ);
    *reinterpret_cast<float4*>(Pr + k4 * 4) = a;
    *reinterpret_cast<float4*>(Pr + DSZ + k4 * 4) = d;
}

// ---------------------------------------------------------------------------
// C[M,1024] = A[M,K] @ B[1024,K]^T   (both row-major, K-contiguous "NT" GEMM)
// BM=BN=128, BK=16, 256 threads, 8x8 register tile per thread.
// M, K multiples of 128/16; N fixed at 1024.
// ---------------------------------------------------------------------------
__global__ void __launch_bounds__(256, 2) gemm_nt(const float* __restrict__ A,
                                                  const float* __restrict__ Bm,
                                                  float* __restrict__ C, int K) {
    const int BM = 128, BN = 128, BK = 16;
    __shared__ float As[BK][BM];
    __shared__ float Bs[BK][BN];

    int bm = blockIdx.y, bn = blockIdx.x;
    int tid = threadIdx.x;
    int tx = tid & 15, ty = tid >> 4;

    const float* Ab = A + (size_t)bm * BM * K;
    const float* Bb = Bm + (size_t)bn * BN * K;

    float acc[8][8];
#pragma unroll
    for (int i = 0; i < 8; i++)
#pragma unroll
        for (int j = 0; j < 8; j++) acc[i][j] = 0.0f;

    int lr = tid >> 2;          // 0..63
    int lc = (tid & 3) * 4;     // 0,4,8,12

    for (int k0 = 0; k0 < K; k0 += BK) {
#pragma unroll
        for (int h = 0; h < 2; h++) {
            int row = lr + h * 64;
            float4 v = *reinterpret_cast<const float4*>(Ab + (size_t)row * K + k0 + lc);
            As[lc + 0][row] = v.x; As[lc + 1][row] = v.y;
            As[lc + 2][row] = v.z; As[lc + 3][row] = v.w;
        }
#pragma unroll
        for (int h = 0; h < 2; h++) {
            int row = lr + h * 64;
            float4 v = *reinterpret_cast<const float4*>(Bb + (size_t)row * K + k0 + lc);
            Bs[lc + 0][row] = v.x; Bs[lc + 1][row] = v.y;
            Bs[lc + 2][row] = v.z; Bs[lc + 3][row] = v.w;
        }
        __syncthreads();

#pragma unroll
        for (int kk = 0; kk < BK; kk++) {
            float4 a0 = *reinterpret_cast<const float4*>(&As[kk][ty * 8]);
            float4 a1 = *reinterpret_cast<const float4*>(&As[kk][ty * 8 + 4]);
            float4 b0 = *reinterpret_cast<const float4*>(&Bs[kk][tx * 8]);
            float4 b1 = *reinterpret_cast<const float4*>(&Bs[kk][tx * 8 + 4]);
            float a[8] = {a0.x, a0.y, a0.z, a0.w, a1.x, a1.y, a1.z, a1.w};
            float b[8] = {b0.x, b0.y, b0.z, b0.w, b1.x, b1.y, b1.z, b1.w};
#pragma unroll
            for (int i = 0; i < 8; i++)
#pragma unroll
                for (int j = 0; j < 8; j++) acc[i][j] += a[i] * b[j];
        }
        __syncthreads();
    }

    float* Cb = C + (size_t)(bm * BM + ty * 8) * DSZ + bn * BN + tx * 8;
#pragma unroll
    for (int i = 0; i < 8; i++) {
        *reinterpret_cast<float4*>(Cb + (size_t)i * DSZ) =
            make_float4(acc[i][0], acc[i][1], acc[i][2], acc[i][3]);
        *reinterpret_cast<float4*>(Cb + (size_t)i * DSZ + 4) =
            make_float4(acc[i][4], acc[i][5], acc[i][6], acc[i][7]);
    }
}

// ---------------------------------------------------------------------------
// Block-wide sum over 256 threads (self-synchronizing helper)
// ---------------------------------------------------------------------------
__device__ __forceinline__ float block_sum_256(float v) {
    __shared__ float red[8];
    __shared__ float tot;
    int t = threadIdx.x;
#pragma unroll
    for (int o = 16; o > 0; o >>= 1) v += __shfl_xor_sync(0xffffffffu, v, o);
    __syncthreads();  // protect red/tot from previous call
    if ((t & 31) == 0) red[t >> 5] = v;
    __syncthreads();
    if (t == 0) {
        float s = 0.0f;
#pragma unroll
        for (int i = 0; i < 8; i++) s += red[i];
        tot = s;
    }
    __syncthreads();
    return tot;
}

// ---------------------------------------------------------------------------
// pre = C1[r] + C2[r>>1]; h = silu(LayerNorm(pre)); write H=h and U=silu(h)
// One block (256 threads) per row; each thread owns 4 columns (float4).
// Two-pass variance for accuracy.
// ---------------------------------------------------------------------------
__global__ void __launch_bounds__(256) lnact_kernel(const float* __restrict__ C1,
                                                    const float* __restrict__ C2,
                                                    const float* __restrict__ gamma,
                                                    const float* __restrict__ beta,
                                                    float* __restrict__ Hout,
                                                    float* __restrict__ Uout) {
    int r = blockIdx.x;
    int t = threadIdx.x;
    float4 v1 = *reinterpret_cast<const float4*>(C1 + (size_t)r * DSZ + t * 4);
    float4 v2 = *reinterpret_cast<const float4*>(C2 + (size_t)(r >> 1) * DSZ + t * 4);
    float x0 = v1.x + v2.x, x1 = v1.y + v2.y, x2 = v1.z + v2.z, x3 = v1.w + v2.w;

    float mu = block_sum_256(x0 + x1 + x2 + x3) * (1.0f / DSZ);
    float d0 = x0 - mu, d1 = x1 - mu, d2 = x2 - mu, d3 = x3 - mu;
    float var = block_sum_256(d0 * d0 + d1 * d1 + d2 * d2 + d3 * d3) * (1.0f / DSZ);
    float rs = rsqrtf(var + LN_EPSf);

    float4 g4 = *reinterpret_cast<const float4*>(gamma + t * 4);
    float4 b4 = *reinterpret_cast<const float4*>(beta + t * 4);
    float h0 = silu_f(d0 * rs * g4.x + b4.x);
    float h1 = silu_f(d1 * rs * g4.y + b4.y);
    float h2 = silu_f(d2 * rs * g4.z + b4.z);
    float h3 = silu_f(d3 * rs * g4.w + b4.w);

    *reinterpret_cast<float4*>(Hout + (size_t)r * DSZ + t * 4) =
        make_float4(h0, h1, h2, h3);
    *reinterpret_cast<float4*>(Uout + (size_t)r * DSZ + t * 4) =
        make_float4(silu_f(h0), silu_f(h1), silu_f(h2), silu_f(h3));
}

// ---------------------------------------------------------------------------
// out[b] = (1/S) * sum_s sum_d H[b,s,d] * W[d] + out_b
// One block (1024 threads = one per d) per batch element.
// ---------------------------------------------------------------------------
__global__ void __launch_bounds__(1024) pool_kernel(const float* __restrict__ H,
                                                    const float* __restrict__ W,
                                                    const float* __restrict__ ob,
                                                    float* __restrict__ out) {
    __shared__ float red[32];
    int b = blockIdx.x, t = threadIdx.x;
    const float* Hb = H + (size_t)b * SSZ * DSZ + t;
    float cs = 0.0f;
#pragma unroll 8
    for (int s = 0; s < SSZ; s++) cs += Hb[(size_t)s * DSZ];
    float acc = cs * W[t];
#pragma unroll
    for (int o = 16; o > 0; o >>= 1) acc += __shfl_xor_sync(0xffffffffu, acc, o);
    if ((t & 31) == 0) red[t >> 5] = acc;
    __syncthreads();
    if (t < 32) {
        float v = red[t];
#pragma unroll
        for (int o = 16; o > 0; o >>= 1) v += __shfl_xor_sync(0xffffffffu, v, o);
        if (t == 0) out[b] = v * (1.0f / SSZ) + ob[0];
    }
}

// ---------------------------------------------------------------------------
// Launch
// ---------------------------------------------------------------------------
extern "C" void kernel_launch(void* const* d_in, const int* in_sizes, int n_in,
                              void* d_out, int out_size) {
    const float* x     = (const float*)d_in[0];
    const float* baseW = (const float*)d_in[1];
    const float* wavW  = (const float*)d_in[2];
    const float* lng   = (const float*)d_in[3];
    const float* lnb   = (const float*)d_in[4];
    const float* outW  = (const float*)d_in[5];
    const float* outb  = (const float*)d_in[6];
    float* out = (float*)d_out;

    float *H, *U, *P, *C1, *C2;
    cudaGetSymbolAddress((void**)&H, g_H);
    cudaGetSymbolAddress((void**)&U, g_U);
    cudaGetSymbolAddress((void**)&P, g_P);
    cudaGetSymbolAddress((void**)&C1, g_C1);
    cudaGetSymbolAddress((void**)&C2, g_C2);

    // U0 = silu(x)
    silu_kernel<<<(NTOK * DSZ) / 1024, 256>>>(x, U);

    const float* hin = x;
    for (int l = 0; l < LSZ; l++) {
        pairs_kernel<<<(NPAIR * DSZ) / 1024, 256>>>(hin, P);
        gemm_nt<<<dim3(DSZ / 128, NTOK / 128), 256>>>(
            U, baseW + (size_t)l * DSZ * DSZ, C1, DSZ);
        gemm_nt<<<dim3(DSZ / 128, NPAIR / 128), 256>>>(
            P, wavW + (size_t)l * DSZ * 2 * DSZ, C2, 2 * DSZ);
        lnact_kernel<<<NTOK, 256>>>(C1, C2, lng + l * DSZ, lnb + l * DSZ, H, U);
        hin = H;
    }
    pool_kernel<<<BSZ, 1024>>>(H, outW, outb, out);
}

// round 4
// speedup vs baseline: 2.5763x; 2.5763x over previous
#include <cuda_runtime.h>
#include <cuda_bf16.h>
#include <math.h>
#include <stdint.h>

// Problem constants
#define BSZ 32
#define SSZ 512
#define DSZ 1024
#define LSZ 3
#define NTOK (BSZ * SSZ)   // 16384
#define NPAIR (NTOK / 2)   // 8192
#define INV_SQRT2f 0.70710678118654752440f
#define LN_EPSf 1e-5f

// ---------------------------------------------------------------------------
// Scratch (device globals)
// ---------------------------------------------------------------------------
__device__ float g_H[(size_t)NTOK * DSZ];
__device__ float g_C1[(size_t)NTOK * DSZ];
__device__ float g_C2[(size_t)NPAIR * DSZ];
__device__ __nv_bfloat16 g_Uh[(size_t)NTOK * DSZ];
__device__ __nv_bfloat16 g_Ul[(size_t)NTOK * DSZ];
__device__ __nv_bfloat16 g_Ph[(size_t)NPAIR * 2 * DSZ];
__device__ __nv_bfloat16 g_Pl[(size_t)NPAIR * 2 * DSZ];
__device__ __nv_bfloat16 g_bWh[(size_t)LSZ * DSZ * DSZ];
__device__ __nv_bfloat16 g_bWl[(size_t)LSZ * DSZ * DSZ];
__device__ __nv_bfloat16 g_wWh[(size_t)LSZ * DSZ * 2 * DSZ];
__device__ __nv_bfloat16 g_wWl[(size_t)LSZ * DSZ * 2 * DSZ];

__device__ __forceinline__ float silu_f(float x) {
    return x / (1.0f + __expf(-x));
}

__device__ __forceinline__ void split_bf(float x, __nv_bfloat16& h, __nv_bfloat16& l) {
    h = __float2bfloat16_rn(x);
    l = __float2bfloat16_rn(x - __bfloat162float(h));
}

__device__ __forceinline__ uint32_t pack2bf(__nv_bfloat16 a, __nv_bfloat16 b) {
    __nv_bfloat162 v = __nv_bfloat162(a, b);
    return *reinterpret_cast<uint32_t*>(&v);
}

// ---------------------------------------------------------------------------
// PTX helpers (sm_80-baseline: cp.async, ldmatrix, mma.sync)
// ---------------------------------------------------------------------------
__device__ __forceinline__ uint32_t smem_u32(const void* p) {
    uint32_t a;
    asm("{ .reg .u64 t; cvta.to.shared.u64 t, %1; cvt.u32.u64 %0, t; }" : "=r"(a) : "l"(p));
    return a;
}
#define CP_ASYNC16(smem, gmem) \
    asm volatile("cp.async.cg.shared.global [%0], [%1], 16;" \
                 :: "r"((uint32_t)(smem)), "l"(gmem) : "memory")
#define CP_COMMIT() asm volatile("cp.async.commit_group;" ::: "memory")
#define CP_WAIT(n) asm volatile("cp.async.wait_group %0;" :: "n"(n) : "memory")

__device__ __forceinline__ void ldsm_x4(uint32_t& r0, uint32_t& r1, uint32_t& r2,
                                        uint32_t& r3, uint32_t addr) {
    asm volatile("ldmatrix.sync.aligned.m8n8.x4.shared.b16 {%0,%1,%2,%3}, [%4];"
                 : "=r"(r0), "=r"(r1), "=r"(r2), "=r"(r3) : "r"(addr));
}

__device__ __forceinline__ void mma16816(float* c, const uint32_t* a, uint32_t b0,
                                         uint32_t b1) {
    asm volatile(
        "mma.sync.aligned.m16n8k16.row.col.f32.bf16.bf16.f32 "
        "{%0,%1,%2,%3}, {%4,%5,%6,%7}, {%8,%9}, {%0,%1,%2,%3};"
        : "+f"(c[0]), "+f"(c[1]), "+f"(c[2]), "+f"(c[3])
        : "r"(a[0]), "r"(a[1]), "r"(a[2]), "r"(a[3]), "r"(b0), "r"(b1));
}

// ---------------------------------------------------------------------------
// Split-bf16 tensor-core GEMM: C[M,1024] = (Ah+Al)[M,K] @ (Bh+Bl)[1024,K]^T
// dropping Al*Bl (~2^-18). CTA tile 128x128, BK=32, 8 warps (64x32 each),
// 3-stage cp.async pipeline. Rows are 64B (32 bf16); 16B-chunk swizzle
// chunk' = chunk ^ ((row>>1)&3) -> conflict-free ldmatrix.
// ---------------------------------------------------------------------------
#define BK 32
#define ROWB 64                       // bytes per smem row
#define MAT_BYTES (128 * ROWB)        // 8 KB per operand tile
#define STAGE_BYTES (4 * MAT_BYTES)   // Ah, Al, Bh, Bl = 32 KB
#define NSTAGE 3
#define GEMM_SMEM (NSTAGE * STAGE_BYTES)

__device__ __forceinline__ uint32_t swz(int row, int chunk) {
    return (uint32_t)(row * ROWB + ((chunk ^ ((row >> 1) & 3)) << 4));
}

__device__ __forceinline__ void load_stage(uint32_t st, const __nv_bfloat16* Ah,
                                           const __nv_bfloat16* Al,
                                           const __nv_bfloat16* Bh,
                                           const __nv_bfloat16* Bl,
                                           int K, int slab, int tid) {
    const __nv_bfloat16* srcs[4] = {Ah, Al, Bh, Bl};
#pragma unroll
    for (int m = 0; m < 4; m++) {
        uint32_t mbase = st + m * MAT_BYTES;
        const __nv_bfloat16* src = srcs[m];
#pragma unroll
        for (int j = 0; j < 2; j++) {
            int chunk = tid + j * 256;      // 512 x 16B chunks per 8KB tile
            int row = chunk >> 2;           // 0..127
            int c = chunk & 3;
            const void* g = src + (size_t)row * K + slab * BK + c * 8;
            CP_ASYNC16(mbase + swz(row, c), g);
        }
    }
}

__global__ void __launch_bounds__(256) gemm_mma(const __nv_bfloat16* __restrict__ Ah,
                                                const __nv_bfloat16* __restrict__ Al,
                                                const __nv_bfloat16* __restrict__ Bh,
                                                const __nv_bfloat16* __restrict__ Bl,
                                                float* __restrict__ C, int K) {
    extern __shared__ char smem[];
    const uint32_t sb = smem_u32(smem);
    const int tid = threadIdx.x;
    const int wid = tid >> 5;
    const int lane = tid & 31;
    const int wm = wid >> 2;            // 0..1  -> m offset wm*64
    const int wn = wid & 3;             // 0..3  -> n offset wn*32
    const int bm = blockIdx.y, bn = blockIdx.x;

    const __nv_bfloat16* Aht = Ah + (size_t)bm * 128 * K;
    const __nv_bfloat16* Alt = Al + (size_t)bm * 128 * K;
    const __nv_bfloat16* Bht = Bh + (size_t)bn * 128 * K;
    const __nv_bfloat16* Blt = Bl + (size_t)bn * 128 * K;

    // ldmatrix per-lane row indices (fixed): A tiles mt=0..3, B pairs np=0..1
    int arow[4], brow[2];
#pragma unroll
    for (int mt = 0; mt < 4; mt++) arow[mt] = wm * 64 + mt * 16 + (lane & 15);
#pragma unroll
    for (int np = 0; np < 2; np++) brow[np] = wn * 32 + np * 16 + (lane & 15);
    const int lchunk = lane >> 4;       // 0/1: k-halves within a kstep

    float acc[4][4][4];
#pragma unroll
    for (int i = 0; i < 4; i++)
#pragma unroll
        for (int j = 0; j < 4; j++)
#pragma unroll
            for (int q = 0; q < 4; q++) acc[i][j][q] = 0.0f;

    const int nslab = K / BK;
    load_stage(sb, Aht, Alt, Bht, Blt, K, 0, tid);
    CP_COMMIT();
    load_stage(sb + STAGE_BYTES, Aht, Alt, Bht, Blt, K, 1, tid);
    CP_COMMIT();

    for (int i = 0; i < nslab; i++) {
        CP_WAIT(1);
        __syncthreads();
        if (i + 2 < nslab) {
            load_stage(sb + ((i + 2) % NSTAGE) * STAGE_BYTES,
                       Aht, Alt, Bht, Blt, K, i + 2, tid);
            CP_COMMIT();
        }

        const uint32_t st = sb + (i % NSTAGE) * STAGE_BYTES;
        const uint32_t sAh = st, sAl = st + MAT_BYTES;
        const uint32_t sBh = st + 2 * MAT_BYTES, sBl = st + 3 * MAT_BYTES;

#pragma unroll
        for (int ks = 0; ks < BK / 16; ks++) {
            const int kc = lchunk + ks * 2;
            uint32_t ah[4][4], bh[2][4], bl[2][4];
#pragma unroll
            for (int mt = 0; mt < 4; mt++)
                ldsm_x4(ah[mt][0], ah[mt][1], ah[mt][2], ah[mt][3],
                        sAh + swz(arow[mt], kc));
#pragma unroll
            for (int np = 0; np < 2; np++)
                ldsm_x4(bh[np][0], bh[np][1], bh[np][2], bh[np][3],
                        sBh + swz(brow[np], kc));
#pragma unroll
            for (int np = 0; np < 2; np++)
                ldsm_x4(bl[np][0], bl[np][1], bl[np][2], bl[np][3],
                        sBl + swz(brow[np], kc));

            // Ah*Bh and Ah*Bl
#pragma unroll
            for (int mt = 0; mt < 4; mt++)
#pragma unroll
                for (int nt = 0; nt < 4; nt++) {
                    // n-tile nt: pair np=nt>>1, sub s=nt&1: b0=r[s], b1=r[s+2]
                    mma16816(acc[mt][nt], ah[mt], bh[nt >> 1][nt & 1],
                             bh[nt >> 1][(nt & 1) + 2]);
                    mma16816(acc[mt][nt], ah[mt], bl[nt >> 1][nt & 1],
                             bl[nt >> 1][(nt & 1) + 2]);
                }
            // Al*Bh
            uint32_t al[4];
#pragma unroll
            for (int mt = 0; mt < 4; mt++) {
                ldsm_x4(al[0], al[1], al[2], al[3], sAl + swz(arow[mt], kc));
#pragma unroll
                for (int nt = 0; nt < 4; nt++)
                    mma16816(acc[mt][nt], al, bh[nt >> 1][nt & 1],
                             bh[nt >> 1][(nt & 1) + 2]);
            }
        }
    }

    // Epilogue: write fp32 C
    const int rbase = bm * 128 + wm * 64 + (lane >> 2);
    const int cbase = bn * 128 + wn * 32 + (lane & 3) * 2;
#pragma unroll
    for (int mt = 0; mt < 4; mt++)
#pragma unroll
        for (int nt = 0; nt < 4; nt++) {
            int r0 = rbase + mt * 16;
            int col = cbase + nt * 8;
            *reinterpret_cast<float2*>(C + (size_t)r0 * DSZ + col) =
                make_float2(acc[mt][nt][0], acc[mt][nt][1]);
            *reinterpret_cast<float2*>(C + (size_t)(r0 + 8) * DSZ + col) =
                make_float2(acc[mt][nt][2], acc[mt][nt][3]);
        }
}

// ---------------------------------------------------------------------------
// Elementwise kernels
// ---------------------------------------------------------------------------
__global__ void __launch_bounds__(256) wsplit_kernel(const float* __restrict__ in,
                                                     __nv_bfloat16* __restrict__ hi,
                                                     __nv_bfloat16* __restrict__ lo) {
    size_t i = ((size_t)blockIdx.x * blockDim.x + threadIdx.x) * 4;
    float4 v = *reinterpret_cast<const float4*>(in + i);
    __nv_bfloat16 h0, h1, h2, h3, l0, l1, l2, l3;
    split_bf(v.x, h0, l0); split_bf(v.y, h1, l1);
    split_bf(v.z, h2, l2); split_bf(v.w, h3, l3);
    *reinterpret_cast<uint2*>(hi + i) = make_uint2(pack2bf(h0, h1), pack2bf(h2, h3));
    *reinterpret_cast<uint2*>(lo + i) = make_uint2(pack2bf(l0, l1), pack2bf(l2, l3));
}

__global__ void __launch_bounds__(256) silu_split_kernel(const float* __restrict__ in,
                                                         __nv_bfloat16* __restrict__ hi,
                                                         __nv_bfloat16* __restrict__ lo) {
    size_t i = ((size_t)blockIdx.x * blockDim.x + threadIdx.x) * 4;
    float4 v = *reinterpret_cast<const float4*>(in + i);
    float u0 = silu_f(v.x), u1 = silu_f(v.y), u2 = silu_f(v.z), u3 = silu_f(v.w);
    __nv_bfloat16 h0, h1, h2, h3, l0, l1, l2, l3;
    split_bf(u0, h0, l0); split_bf(u1, h1, l1);
    split_bf(u2, h2, l2); split_bf(u3, h3, l3);
    *reinterpret_cast<uint2*>(hi + i) = make_uint2(pack2bf(h0, h1), pack2bf(h2, h3));
    *reinterpret_cast<uint2*>(lo + i) = make_uint2(pack2bf(l0, l1), pack2bf(l2, l3));
}

__global__ void __launch_bounds__(256) pairs_split_kernel(const float* __restrict__ Hin,
                                                          __nv_bfloat16* __restrict__ Ph,
                                                          __nv_bfloat16* __restrict__ Pl) {
    size_t idx = (size_t)blockIdx.x * blockDim.x + threadIdx.x;
    int k4 = (int)(idx % (DSZ / 4));
    size_t p = idx / (DSZ / 4);
    float4 e = *reinterpret_cast<const float4*>(Hin + (2 * p) * DSZ + k4 * 4);
    float4 o = *reinterpret_cast<const float4*>(Hin + (2 * p + 1) * DSZ + k4 * 4);
    float a0 = (e.x + o.x) * INV_SQRT2f, a1 = (e.y + o.y) * INV_SQRT2f;
    float a2 = (e.z + o.z) * INV_SQRT2f, a3 = (e.w + o.w) * INV_SQRT2f;
    float d0 = (e.x - o.x) * INV_SQRT2f, d1 = (e.y - o.y) * INV_SQRT2f;
    float d2 = (e.z - o.z) * INV_SQRT2f, d3 = (e.w - o.w) * INV_SQRT2f;
    size_t ra = p * (2 * DSZ) + k4 * 4;
    size_t rd = ra + DSZ;
    __nv_bfloat16 h0, h1, h2, h3, l0, l1, l2, l3;
    split_bf(a0, h0, l0); split_bf(a1, h1, l1); split_bf(a2, h2, l2); split_bf(a3, h3, l3);
    *reinterpret_cast<uint2*>(Ph + ra) = make_uint2(pack2bf(h0, h1), pack2bf(h2, h3));
    *reinterpret_cast<uint2*>(Pl + ra) = make_uint2(pack2bf(l0, l1), pack2bf(l2, l3));
    split_bf(d0, h0, l0); split_bf(d1, h1, l1); split_bf(d2, h2, l2); split_bf(d3, h3, l3);
    *reinterpret_cast<uint2*>(Ph + rd) = make_uint2(pack2bf(h0, h1), pack2bf(h2, h3));
    *reinterpret_cast<uint2*>(Pl + rd) = make_uint2(pack2bf(l0, l1), pack2bf(l2, l3));
}

__device__ __forceinline__ float block_sum_256(float v) {
    __shared__ float red[8];
    __shared__ float tot;
    int t = threadIdx.x;
#pragma unroll
    for (int o = 16; o > 0; o >>= 1) v += __shfl_xor_sync(0xffffffffu, v, o);
    __syncthreads();
    if ((t & 31) == 0) red[t >> 5] = v;
    __syncthreads();
    if (t == 0) {
        float s = 0.0f;
#pragma unroll
        for (int i = 0; i < 8; i++) s += red[i];
        tot = s;
    }
    __syncthreads();
    return tot;
}

__global__ void __launch_bounds__(256) lnact_kernel(const float* __restrict__ C1,
                                                    const float* __restrict__ C2,
                                                    const float* __restrict__ gamma,
                                                    const float* __restrict__ beta,
                                                    float* __restrict__ Hout,
                                                    __nv_bfloat16* __restrict__ Uh,
                                                    __nv_bfloat16* __restrict__ Ul) {
    int r = blockIdx.x;
    int t = threadIdx.x;
    float4 v1 = *reinterpret_cast<const float4*>(C1 + (size_t)r * DSZ + t * 4);
    float4 v2 = *reinterpret_cast<const float4*>(C2 + (size_t)(r >> 1) * DSZ + t * 4);
    float x0 = v1.x + v2.x, x1 = v1.y + v2.y, x2 = v1.z + v2.z, x3 = v1.w + v2.w;

    float mu = block_sum_256(x0 + x1 + x2 + x3) * (1.0f / DSZ);
    float d0 = x0 - mu, d1 = x1 - mu, d2 = x2 - mu, d3 = x3 - mu;
    float var = block_sum_256(d0 * d0 + d1 * d1 + d2 * d2 + d3 * d3) * (1.0f / DSZ);
    float rs = rsqrtf(var + LN_EPSf);

    float4 g4 = *reinterpret_cast<const float4*>(gamma + t * 4);
    float4 b4 = *reinterpret_cast<const float4*>(beta + t * 4);
    float h0 = silu_f(d0 * rs * g4.x + b4.x);
    float h1 = silu_f(d1 * rs * g4.y + b4.y);
    float h2 = silu_f(d2 * rs * g4.z + b4.z);
    float h3 = silu_f(d3 * rs * g4.w + b4.w);

    *reinterpret_cast<float4*>(Hout + (size_t)r * DSZ + t * 4) =
        make_float4(h0, h1, h2, h3);

    float u0 = silu_f(h0), u1 = silu_f(h1), u2 = silu_f(h2), u3 = silu_f(h3);
    __nv_bfloat16 uh0, uh1, uh2, uh3, ul0, ul1, ul2, ul3;
    split_bf(u0, uh0, ul0); split_bf(u1, uh1, ul1);
    split_bf(u2, uh2, ul2); split_bf(u3, uh3, ul3);
    size_t off = (size_t)r * DSZ + t * 4;
    *reinterpret_cast<uint2*>(Uh + off) = make_uint2(pack2bf(uh0, uh1), pack2bf(uh2, uh3));
    *reinterpret_cast<uint2*>(Ul + off) = make_uint2(pack2bf(ul0, ul1), pack2bf(ul2, ul3));
}

__global__ void __launch_bounds__(1024) pool_kernel(const float* __restrict__ H,
                                                    const float* __restrict__ W,
                                                    const float* __restrict__ ob,
                                                    float* __restrict__ out) {
    __shared__ float red[32];
    int b = blockIdx.x, t = threadIdx.x;
    const float* Hb = H + (size_t)b * SSZ * DSZ + t;
    float cs = 0.0f;
#pragma unroll 8
    for (int s = 0; s < SSZ; s++) cs += Hb[(size_t)s * DSZ];
    float acc = cs * W[t];
#pragma unroll
    for (int o = 16; o > 0; o >>= 1) acc += __shfl_xor_sync(0xffffffffu, acc, o);
    if ((t & 31) == 0) red[t >> 5] = acc;
    __syncthreads();
    if (t < 32) {
        float v = red[t];
#pragma unroll
        for (int o = 16; o > 0; o >>= 1) v += __shfl_xor_sync(0xffffffffu, v, o);
        if (t == 0) out[b] = v * (1.0f / SSZ) + ob[0];
    }
}

// ---------------------------------------------------------------------------
// Launch
// ---------------------------------------------------------------------------
extern "C" void kernel_launch(void* const* d_in, const int* in_sizes, int n_in,
                              void* d_out, int out_size) {
    const float* x     = (const float*)d_in[0];
    const float* baseW = (const float*)d_in[1];
    const float* wavW  = (const float*)d_in[2];
    const float* lng   = (const float*)d_in[3];
    const float* lnb   = (const float*)d_in[4];
    const float* outW  = (const float*)d_in[5];
    const float* outb  = (const float*)d_in[6];
    float* out = (float*)d_out;

    float *H, *C1, *C2;
    __nv_bfloat16 *Uh, *Ul, *Ph, *Pl, *bWh, *bWl, *wWh, *wWl;
    cudaGetSymbolAddress((void**)&H, g_H);
    cudaGetSymbolAddress((void**)&C1, g_C1);
    cudaGetSymbolAddress((void**)&C2, g_C2);
    cudaGetSymbolAddress((void**)&Uh, g_Uh);
    cudaGetSymbolAddress((void**)&Ul, g_Ul);
    cudaGetSymbolAddress((void**)&Ph, g_Ph);
    cudaGetSymbolAddress((void**)&Pl, g_Pl);
    cudaGetSymbolAddress((void**)&bWh, g_bWh);
    cudaGetSymbolAddress((void**)&bWl, g_bWl);
    cudaGetSymbolAddress((void**)&wWh, g_wWh);
    cudaGetSymbolAddress((void**)&wWl, g_wWl);

    cudaFuncSetAttribute(gemm_mma, cudaFuncAttributeMaxDynamicSharedMemorySize,
                         GEMM_SMEM);

    // Split weights (all layers)
    wsplit_kernel<<<(LSZ * DSZ * DSZ) / 1024, 256>>>(baseW, bWh, bWl);
    wsplit_kernel<<<(LSZ * DSZ * 2 * DSZ) / 1024, 256>>>(wavW, wWh, wWl);

    // U0 = split(silu(x))
    silu_split_kernel<<<(NTOK * DSZ) / 1024, 256>>>(x, Uh, Ul);

    const float* hin = x;
    for (int l = 0; l < LSZ; l++) {
        pairs_split_kernel<<<(NPAIR * DSZ) / 1024, 256>>>(hin, Ph, Pl);
        gemm_mma<<<dim3(DSZ / 128, NTOK / 128), 256, GEMM_SMEM>>>(
            Uh, Ul, bWh + (size_t)l * DSZ * DSZ, bWl + (size_t)l * DSZ * DSZ, C1, DSZ);
        gemm_mma<<<dim3(DSZ / 128, NPAIR / 128), 256, GEMM_SMEM>>>(
            Ph, Pl, wWh + (size_t)l * DSZ * 2 * DSZ, wWl + (size_t)l * DSZ * 2 * DSZ,
            C2, 2 * DSZ);
        lnact_kernel<<<NTOK, 256>>>(C1, C2, lng + l * DSZ, lnb + l * DSZ, H, Uh, Ul);
        hin = H;
    }
    pool_kernel<<<BSZ, 1024>>>(H, outW, outb, out);
}

// round 5
// speedup vs baseline: 2.6123x; 1.0140x over previous
#include <cuda_runtime.h>
#include <cuda_bf16.h>
#include <math.h>
#include <stdint.h>

// Problem constants
#define BSZ 32
#define SSZ 512
#define DSZ 1024
#define LSZ 3
#define NTOK (BSZ * SSZ)   // 16384
#define NPAIR (NTOK / 2)   // 8192
#define INV_SQRT2f 0.70710678118654752440f
#define LN_EPSf 1e-5f

// ---------------------------------------------------------------------------
// Scratch (device globals)
// ---------------------------------------------------------------------------
__device__ float g_H[(size_t)NTOK * DSZ];                // hidden fp32 (final layer only)
__device__ float g_C1[(size_t)NTOK * DSZ];
__device__ float g_C2[(size_t)NPAIR * DSZ];
__device__ __nv_bfloat16 g_Uh[(size_t)NTOK * DSZ];       // silu(h) hi/lo
__device__ __nv_bfloat16 g_Ul[(size_t)NTOK * DSZ];
__device__ __nv_bfloat16 g_Hh[(size_t)NTOK * DSZ];       // h hi/lo (wav GEMM input)
__device__ __nv_bfloat16 g_Hl[(size_t)NTOK * DSZ];
__device__ __nv_bfloat16 g_bWh[(size_t)LSZ * DSZ * DSZ];
__device__ __nv_bfloat16 g_bWl[(size_t)LSZ * DSZ * DSZ];
__device__ __nv_bfloat16 g_wWh[(size_t)LSZ * DSZ * 2 * DSZ];  // combined [We|Wo]
__device__ __nv_bfloat16 g_wWl[(size_t)LSZ * DSZ * 2 * DSZ];

__device__ __forceinline__ float silu_f(float x) {
    return x / (1.0f + __expf(-x));
}

__device__ __forceinline__ void split_bf(float x, __nv_bfloat16& h, __nv_bfloat16& l) {
    h = __float2bfloat16_rn(x);
    l = __float2bfloat16_rn(x - __bfloat162float(h));
}

__device__ __forceinline__ uint32_t pack2bf(__nv_bfloat16 a, __nv_bfloat16 b) {
    __nv_bfloat162 v = __nv_bfloat162(a, b);
    return *reinterpret_cast<uint32_t*>(&v);
}

// ---------------------------------------------------------------------------
// PTX helpers (sm_80-baseline: cp.async, ldmatrix, mma.sync)
// ---------------------------------------------------------------------------
__device__ __forceinline__ uint32_t smem_u32(const void* p) {
    uint32_t a;
    asm("{ .reg .u64 t; cvta.to.shared.u64 t, %1; cvt.u32.u64 %0, t; }" : "=r"(a) : "l"(p));
    return a;
}
#define CP_ASYNC16(smem, gmem) \
    asm volatile("cp.async.cg.shared.global [%0], [%1], 16;" \
                 :: "r"((uint32_t)(smem)), "l"(gmem) : "memory")
#define CP_COMMIT() asm volatile("cp.async.commit_group;" ::: "memory")
#define CP_WAIT(n) asm volatile("cp.async.wait_group %0;" :: "n"(n) : "memory")

__device__ __forceinline__ void ldsm_x4(uint32_t& r0, uint32_t& r1, uint32_t& r2,
                                        uint32_t& r3, uint32_t addr) {
    asm volatile("ldmatrix.sync.aligned.m8n8.x4.shared.b16 {%0,%1,%2,%3}, [%4];"
                 : "=r"(r0), "=r"(r1), "=r"(r2), "=r"(r3) : "r"(addr));
}

__device__ __forceinline__ void mma16816(float* c, const uint32_t* a, uint32_t b0,
                                         uint32_t b1) {
    asm volatile(
        "mma.sync.aligned.m16n8k16.row.col.f32.bf16.bf16.f32 "
        "{%0,%1,%2,%3}, {%4,%5,%6,%7}, {%8,%9}, {%0,%1,%2,%3};"
        : "+f"(c[0]), "+f"(c[1]), "+f"(c[2]), "+f"(c[3])
        : "r"(a[0]), "r"(a[1]), "r"(a[2]), "r"(a[3]), "r"(b0), "r"(b1));
}

// ---------------------------------------------------------------------------
// Split-bf16 tensor-core GEMM: C[M,1024] = (Ah+Al)[M,K] @ (Bh+Bl)[1024,K]^T
// dropping Al*Bl (~2^-18). CTA tile 128x128, BK=32, 8 warps (64x32 each),
// 3-stage cp.async pipeline, 16B-chunk swizzle for conflict-free ldmatrix.
// ---------------------------------------------------------------------------
#define BK 32
#define ROWB 64
#define MAT_BYTES (128 * ROWB)        // 8 KB per operand tile
#define STAGE_BYTES (4 * MAT_BYTES)   // Ah, Al, Bh, Bl = 32 KB
#define NSTAGE 3
#define GEMM_SMEM (NSTAGE * STAGE_BYTES)

__device__ __forceinline__ uint32_t swz(int row, int chunk) {
    return (uint32_t)(row * ROWB + ((chunk ^ ((row >> 1) & 3)) << 4));
}

__device__ __forceinline__ void load_stage(uint32_t st, const __nv_bfloat16* Ah,
                                           const __nv_bfloat16* Al,
                                           const __nv_bfloat16* Bh,
                                           const __nv_bfloat16* Bl,
                                           int K, int slab, int tid) {
    const __nv_bfloat16* srcs[4] = {Ah, Al, Bh, Bl};
#pragma unroll
    for (int m = 0; m < 4; m++) {
        uint32_t mbase = st + m * MAT_BYTES;
        const __nv_bfloat16* src = srcs[m];
#pragma unroll
        for (int j = 0; j < 2; j++) {
            int chunk = tid + j * 256;
            int row = chunk >> 2;
            int c = chunk & 3;
            const void* g = src + (size_t)row * K + slab * BK + c * 8;
            CP_ASYNC16(mbase + swz(row, c), g);
        }
    }
}

__global__ void __launch_bounds__(256, 2) gemm_mma(const __nv_bfloat16* __restrict__ Ah,
                                                   const __nv_bfloat16* __restrict__ Al,
                                                   const __nv_bfloat16* __restrict__ Bh,
                                                   const __nv_bfloat16* __restrict__ Bl,
                                                   float* __restrict__ C, int K) {
    extern __shared__ char smem[];
    const uint32_t sb = smem_u32(smem);
    const int tid = threadIdx.x;
    const int wid = tid >> 5;
    const int lane = tid & 31;
    const int wm = wid >> 2;
    const int wn = wid & 3;
    const int bm = blockIdx.y, bn = blockIdx.x;

    const __nv_bfloat16* Aht = Ah + (size_t)bm * 128 * K;
    const __nv_bfloat16* Alt = Al + (size_t)bm * 128 * K;
    const __nv_bfloat16* Bht = Bh + (size_t)bn * 128 * K;
    const __nv_bfloat16* Blt = Bl + (size_t)bn * 128 * K;

    int arow[4], brow[2];
#pragma unroll
    for (int mt = 0; mt < 4; mt++) arow[mt] = wm * 64 + mt * 16 + (lane & 15);
#pragma unroll
    for (int np = 0; np < 2; np++) brow[np] = wn * 32 + np * 16 + (lane & 15);
    const int lchunk = lane >> 4;

    float acc[4][4][4];
#pragma unroll
    for (int i = 0; i < 4; i++)
#pragma unroll
        for (int j = 0; j < 4; j++)
#pragma unroll
            for (int q = 0; q < 4; q++) acc[i][j][q] = 0.0f;

    const int nslab = K / BK;
    load_stage(sb, Aht, Alt, Bht, Blt, K, 0, tid);
    CP_COMMIT();
    load_stage(sb + STAGE_BYTES, Aht, Alt, Bht, Blt, K, 1, tid);
    CP_COMMIT();

    for (int i = 0; i < nslab; i++) {
        CP_WAIT(1);
        __syncthreads();
        if (i + 2 < nslab) {
            load_stage(sb + ((i + 2) % NSTAGE) * STAGE_BYTES,
                       Aht, Alt, Bht, Blt, K, i + 2, tid);
            CP_COMMIT();
        }

        const uint32_t st = sb + (i % NSTAGE) * STAGE_BYTES;
        const uint32_t sAh = st, sAl = st + MAT_BYTES;
        const uint32_t sBh = st + 2 * MAT_BYTES, sBl = st + 3 * MAT_BYTES;

#pragma unroll
        for (int ks = 0; ks < BK / 16; ks++) {
            const int kc = lchunk + ks * 2;
            uint32_t ah[4][4], bh[2][4], bl[2][4];
#pragma unroll
            for (int mt = 0; mt < 4; mt++)
                ldsm_x4(ah[mt][0], ah[mt][1], ah[mt][2], ah[mt][3],
                        sAh + swz(arow[mt], kc));
#pragma unroll
            for (int np = 0; np < 2; np++)
                ldsm_x4(bh[np][0], bh[np][1], bh[np][2], bh[np][3],
                        sBh + swz(brow[np], kc));
#pragma unroll
            for (int np = 0; np < 2; np++)
                ldsm_x4(bl[np][0], bl[np][1], bl[np][2], bl[np][3],
                        sBl + swz(brow[np], kc));

#pragma unroll
            for (int mt = 0; mt < 4; mt++)
#pragma unroll
                for (int nt = 0; nt < 4; nt++) {
                    mma16816(acc[mt][nt], ah[mt], bh[nt >> 1][nt & 1],
                             bh[nt >> 1][(nt & 1) + 2]);
                    mma16816(acc[mt][nt], ah[mt], bl[nt >> 1][nt & 1],
                             bl[nt >> 1][(nt & 1) + 2]);
                }
            uint32_t al[4];
#pragma unroll
            for (int mt = 0; mt < 4; mt++) {
                ldsm_x4(al[0], al[1], al[2], al[3], sAl + swz(arow[mt], kc));
#pragma unroll
                for (int nt = 0; nt < 4; nt++)
                    mma16816(acc[mt][nt], al, bh[nt >> 1][nt & 1],
                             bh[nt >> 1][(nt & 1) + 2]);
            }
        }
    }

    const int rbase = bm * 128 + wm * 64 + (lane >> 2);
    const int cbase = bn * 128 + wn * 32 + (lane & 3) * 2;
#pragma unroll
    for (int mt = 0; mt < 4; mt++)
#pragma unroll
        for (int nt = 0; nt < 4; nt++) {
            int r0 = rbase + mt * 16;
            int col = cbase + nt * 8;
            *reinterpret_cast<float2*>(C + (size_t)r0 * DSZ + col) =
                make_float2(acc[mt][nt][0], acc[mt][nt][1]);
            *reinterpret_cast<float2*>(C + (size_t)(r0 + 8) * DSZ + col) =
                make_float2(acc[mt][nt][2], acc[mt][nt][3]);
        }
}

// ---------------------------------------------------------------------------
// Elementwise / prep kernels
// ---------------------------------------------------------------------------
// hi/lo split of fp32 array (base weights, and x -> Hh/Hl)
__global__ void __launch_bounds__(256) wsplit_kernel(const float* __restrict__ in,
                                                     __nv_bfloat16* __restrict__ hi,
                                                     __nv_bfloat16* __restrict__ lo) {
    size_t i = ((size_t)blockIdx.x * blockDim.x + threadIdx.x) * 4;
    float4 v = *reinterpret_cast<const float4*>(in + i);
    __nv_bfloat16 h0, h1, h2, h3, l0, l1, l2, l3;
    split_bf(v.x, h0, l0); split_bf(v.y, h1, l1);
    split_bf(v.z, h2, l2); split_bf(v.w, h3, l3);
    *reinterpret_cast<uint2*>(hi + i) = make_uint2(pack2bf(h0, h1), pack2bf(h2, h3));
    *reinterpret_cast<uint2*>(lo + i) = make_uint2(pack2bf(l0, l1), pack2bf(l2, l3));
}

// Combine wavelet weights: row n = [Wa_n | Wd_n] -> [(Wa+Wd)/sqrt2 | (Wa-Wd)/sqrt2]
// then hi/lo split. One thread per (row, k4) over k<D.
__global__ void __launch_bounds__(256) wavprep_kernel(const float* __restrict__ wavW,
                                                      __nv_bfloat16* __restrict__ hi,
                                                      __nv_bfloat16* __restrict__ lo) {
    size_t idx = (size_t)blockIdx.x * blockDim.x + threadIdx.x;  // LSZ*DSZ*(DSZ/4)
    int k4 = (int)(idx % (DSZ / 4));
    size_t row = idx / (DSZ / 4);                                // l*DSZ + n
    const float* base = wavW + row * (2 * DSZ);
    float4 wa = *reinterpret_cast<const float4*>(base + k4 * 4);
    float4 wd = *reinterpret_cast<const float4*>(base + DSZ + k4 * 4);
    float e0 = (wa.x + wd.x) * INV_SQRT2f, e1 = (wa.y + wd.y) * INV_SQRT2f;
    float e2 = (wa.z + wd.z) * INV_SQRT2f, e3 = (wa.w + wd.w) * INV_SQRT2f;
    float o0 = (wa.x - wd.x) * INV_SQRT2f, o1 = (wa.y - wd.y) * INV_SQRT2f;
    float o2 = (wa.z - wd.z) * INV_SQRT2f, o3 = (wa.w - wd.w) * INV_SQRT2f;
    size_t re = row * (2 * DSZ) + k4 * 4;
    size_t ro = re + DSZ;
    __nv_bfloat16 h0, h1, h2, h3, l0, l1, l2, l3;
    split_bf(e0, h0, l0); split_bf(e1, h1, l1); split_bf(e2, h2, l2); split_bf(e3, h3, l3);
    *reinterpret_cast<uint2*>(hi + re) = make_uint2(pack2bf(h0, h1), pack2bf(h2, h3));
    *reinterpret_cast<uint2*>(lo + re) = make_uint2(pack2bf(l0, l1), pack2bf(l2, l3));
    split_bf(o0, h0, l0); split_bf(o1, h1, l1); split_bf(o2, h2, l2); split_bf(o3, h3, l3);
    *reinterpret_cast<uint2*>(hi + ro) = make_uint2(pack2bf(h0, h1), pack2bf(h2, h3));
    *reinterpret_cast<uint2*>(lo + ro) = make_uint2(pack2bf(l0, l1), pack2bf(l2, l3));
}

// U = split(silu(x))
__global__ void __launch_bounds__(256) silu_split_kernel(const float* __restrict__ in,
                                                         __nv_bfloat16* __restrict__ hi,
                                                         __nv_bfloat16* __restrict__ lo) {
    size_t i = ((size_t)blockIdx.x * blockDim.x + threadIdx.x) * 4;
    float4 v = *reinterpret_cast<const float4*>(in + i);
    float u0 = silu_f(v.x), u1 = silu_f(v.y), u2 = silu_f(v.z), u3 = silu_f(v.w);
    __nv_bfloat16 h0, h1, h2, h3, l0, l1, l2, l3;
    split_bf(u0, h0, l0); split_bf(u1, h1, l1);
    split_bf(u2, h2, l2); split_bf(u3, h3, l3);
    *reinterpret_cast<uint2*>(hi + i) = make_uint2(pack2bf(h0, h1), pack2bf(h2, h3));
    *reinterpret_cast<uint2*>(lo + i) = make_uint2(pack2bf(l0, l1), pack2bf(l2, l3));
}

__device__ __forceinline__ float block_sum_256(float v) {
    __shared__ float red[8];
    __shared__ float tot;
    int t = threadIdx.x;
#pragma unroll
    for (int o = 16; o > 0; o >>= 1) v += __shfl_xor_sync(0xffffffffu, v, o);
    __syncthreads();
    if ((t & 31) == 0) red[t >> 5] = v;
    __syncthreads();
    if (t == 0) {
        float s = 0.0f;
#pragma unroll
        for (int i = 0; i < 8; i++) s += red[i];
        tot = s;
    }
    __syncthreads();
    return tot;
}

// h = silu(LN(C1[r] + C2[r>>1])).
// final=0: write split(h)->Hh/Hl and split(silu(h))->Uh/Ul (no fp32 H).
// final=1: write fp32 H only (for pooling).
__global__ void __launch_bounds__(256) lnact_kernel(const float* __restrict__ C1,
                                                    const float* __restrict__ C2,
                                                    const float* __restrict__ gamma,
                                                    const float* __restrict__ beta,
                                                    float* __restrict__ Hout,
                                                    __nv_bfloat16* __restrict__ Hh,
                                                    __nv_bfloat16* __restrict__ Hl,
                                                    __nv_bfloat16* __restrict__ Uh,
                                                    __nv_bfloat16* __restrict__ Ul,
                                                    int final_layer) {
    int r = blockIdx.x;
    int t = threadIdx.x;
    float4 v1 = *reinterpret_cast<const float4*>(C1 + (size_t)r * DSZ + t * 4);
    float4 v2 = *reinterpret_cast<const float4*>(C2 + (size_t)(r >> 1) * DSZ + t * 4);
    float x0 = v1.x + v2.x, x1 = v1.y + v2.y, x2 = v1.z + v2.z, x3 = v1.w + v2.w;

    float mu = block_sum_256(x0 + x1 + x2 + x3) * (1.0f / DSZ);
    float d0 = x0 - mu, d1 = x1 - mu, d2 = x2 - mu, d3 = x3 - mu;
    float var = block_sum_256(d0 * d0 + d1 * d1 + d2 * d2 + d3 * d3) * (1.0f / DSZ);
    float rs = rsqrtf(var + LN_EPSf);

    float4 g4 = *reinterpret_cast<const float4*>(gamma + t * 4);
    float4 b4 = *reinterpret_cast<const float4*>(beta + t * 4);
    float h0 = silu_f(d0 * rs * g4.x + b4.x);
    float h1 = silu_f(d1 * rs * g4.y + b4.y);
    float h2 = silu_f(d2 * rs * g4.z + b4.z);
    float h3 = silu_f(d3 * rs * g4.w + b4.w);

    size_t off = (size_t)r * DSZ + t * 4;
    if (final_layer) {
        *reinterpret_cast<float4*>(Hout + off) = make_float4(h0, h1, h2, h3);
        return;
    }

    __nv_bfloat16 a0, a1, a2, a3, c0, c1, c2, c3;
    split_bf(h0, a0, c0); split_bf(h1, a1, c1);
    split_bf(h2, a2, c2); split_bf(h3, a3, c3);
    *reinterpret_cast<uint2*>(Hh + off) = make_uint2(pack2bf(a0, a1), pack2bf(a2, a3));
    *reinterpret_cast<uint2*>(Hl + off) = make_uint2(pack2bf(c0, c1), pack2bf(c2, c3));

    float u0 = silu_f(h0), u1 = silu_f(h1), u2 = silu_f(h2), u3 = silu_f(h3);
    split_bf(u0, a0, c0); split_bf(u1, a1, c1);
    split_bf(u2, a2, c2); split_bf(u3, a3, c3);
    *reinterpret_cast<uint2*>(Uh + off) = make_uint2(pack2bf(a0, a1), pack2bf(a2, a3));
    *reinterpret_cast<uint2*>(Ul + off) = make_uint2(pack2bf(c0, c1), pack2bf(c2, c3));
}

__global__ void __launch_bounds__(1024) pool_kernel(const float* __restrict__ H,
                                                    const float* __restrict__ W,
                                                    const float* __restrict__ ob,
                                                    float* __restrict__ out) {
    __shared__ float red[32];
    int b = blockIdx.x, t = threadIdx.x;
    const float* Hb = H + (size_t)b * SSZ * DSZ + t;
    float cs = 0.0f;
#pragma unroll 8
    for (int s = 0; s < SSZ; s++) cs += Hb[(size_t)s * DSZ];
    float acc = cs * W[t];
#pragma unroll
    for (int o = 16; o > 0; o >>= 1) acc += __shfl_xor_sync(0xffffffffu, acc, o);
    if ((t & 31) == 0) red[t >> 5] = acc;
    __syncthreads();
    if (t < 32) {
        float v = red[t];
#pragma unroll
        for (int o = 16; o > 0; o >>= 1) v += __shfl_xor_sync(0xffffffffu, v, o);
        if (t == 0) out[b] = v * (1.0f / SSZ) + ob[0];
    }
}

// ---------------------------------------------------------------------------
// Launch
// ---------------------------------------------------------------------------
extern "C" void kernel_launch(void* const* d_in, const int* in_sizes, int n_in,
                              void* d_out, int out_size) {
    const float* x     = (const float*)d_in[0];
    const float* baseW = (const float*)d_in[1];
    const float* wavW  = (const float*)d_in[2];
    const float* lng   = (const float*)d_in[3];
    const float* lnb   = (const float*)d_in[4];
    const float* outW  = (const float*)d_in[5];
    const float* outb  = (const float*)d_in[6];
    float* out = (float*)d_out;

    float *H, *C1, *C2;
    __nv_bfloat16 *Uh, *Ul, *Hh, *Hl, *bWh, *bWl, *wWh, *wWl;
    cudaGetSymbolAddress((void**)&H, g_H);
    cudaGetSymbolAddress((void**)&C1, g_C1);
    cudaGetSymbolAddress((void**)&C2, g_C2);
    cudaGetSymbolAddress((void**)&Uh, g_Uh);
    cudaGetSymbolAddress((void**)&Ul, g_Ul);
    cudaGetSymbolAddress((void**)&Hh, g_Hh);
    cudaGetSymbolAddress((void**)&Hl, g_Hl);
    cudaGetSymbolAddress((void**)&bWh, g_bWh);
    cudaGetSymbolAddress((void**)&bWl, g_bWl);
    cudaGetSymbolAddress((void**)&wWh, g_wWh);
    cudaGetSymbolAddress((void**)&wWl, g_wWl);

    cudaFuncSetAttribute(gemm_mma, cudaFuncAttributeMaxDynamicSharedMemorySize,
                         GEMM_SMEM);

    // Weight prep
    wsplit_kernel<<<(LSZ * DSZ * DSZ) / 1024, 256>>>(baseW, bWh, bWl);
    wavprep_kernel<<<(LSZ * DSZ * (DSZ / 4)) / 256, 256>>>(wavW, wWh, wWl);

    // Layer-0 inputs: Hh/Hl = split(x), Uh/Ul = split(silu(x))
    wsplit_kernel<<<(NTOK * DSZ) / 1024, 256>>>(x, Hh, Hl);
    silu_split_kernel<<<(NTOK * DSZ) / 1024, 256>>>(x, Uh, Ul);

    for (int l = 0; l < LSZ; l++) {
        // base: U[16384,1024] @ bW^T
        gemm_mma<<<dim3(DSZ / 128, NTOK / 128), 256, GEMM_SMEM>>>(
            Uh, Ul, bWh + (size_t)l * DSZ * DSZ, bWl + (size_t)l * DSZ * DSZ, C1, DSZ);
        // wav: H viewed as [8192, 2048] @ combined wW^T
        gemm_mma<<<dim3(DSZ / 128, NPAIR / 128), 256, GEMM_SMEM>>>(
            Hh, Hl, wWh + (size_t)l * DSZ * 2 * DSZ, wWl + (size_t)l * DSZ * 2 * DSZ,
            C2, 2 * DSZ);
        lnact_kernel<<<NTOK, 256>>>(C1, C2, lng + l * DSZ, lnb + l * DSZ,
                                    H, Hh, Hl, Uh, Ul, (l == LSZ - 1) ? 1 : 0);
    }
    pool_kernel<<<BSZ, 1024>>>(H, outW, outb, out);
}